// round 16
// baseline (speedup 1.0000x reference)
#include <cuda_runtime.h>
#include <cuda_fp16.h>
#include <cstdint>

// Inputs (metadata order):
//   d_in[0] weight : float32 [N_NODES * 128]
//   d_in[1] cj     : float32 [N_NODES]
//   d_in[2] ci     : float32 [N_NODES]
//   d_in[3] src    : int32   [N_EDGES]
//   d_in[4] dst    : int32   [N_EDGES]
// Output: float32 [N_NODES * 128]
//
// h[d] = ci[d] * sum_{e: dst_e = d} weight[src_e] * cj[src_e]
//
// 2-kernel pipeline:
//   k_build  : ONE persistent co-resident kernel (148 blocks x 1024; SM
//              capacity 2048 threads guarantees all blocks resident even in
//              worst-case packing) doing
//                phase 1: dst histogram w/ rank capture  +  W'=fp16(weight*cj)
//                phase 2: block-local scan of counts
//                phase 3: cross-block prefix -> offsets/cursor
//                phase 4: atomic-free scatter (pos = offsets[dst]+rank)
//              separated by sense-reversing grid barriers.
//   k_gather : one warp per dst node; 8-deep unrolled fp16 gathers,
//              HADD2 pair pre-reduction (measured rel_err 2.87e-4 vs 1e-3
//              gate), fp32 accumulation, single 512B store.

static constexpr int MAX_NODES  = 100000;
static constexpr int MAX_EDGES  = 1600000;
static constexpr int FEAT4      = 32;           // 128 floats = 32 float4
static constexpr int FEATH2     = 32;           // 128 halves = 32 uint2
static constexpr int NB         = 148;          // one block per SM
static constexpr int TPB        = 1024;

__device__ int g_counts[MAX_NODES];             // zero-init; re-zeroed by gather
__device__ int g_offsets[MAX_NODES];            // segment start
__device__ int g_cursor[MAX_NODES];             // segment end
__device__ int g_blocksums[NB];
__device__ int g_rank[MAX_EDGES];               // per-edge rank within its dst
__device__ __align__(16) int g_edge_src[MAX_EDGES];  // dst-sorted src ids
__device__ uint2 g_wh[MAX_NODES * FEATH2];      // fp16 W' = weight*cj (25.6 MB)

// sense-reversing grid barrier state (generation never resets; arrive
// returns to 0 after each release, so state is replay-invariant)
__device__ unsigned int g_bar_arrive = 0;
__device__ volatile unsigned int g_bar_gen = 0;

__device__ __forceinline__ void grid_barrier() {
    __syncthreads();
    __threadfence();                             // publish this block's writes
    if (threadIdx.x == 0) {
        unsigned int gen = g_bar_gen;            // read before arriving
        if (atomicAdd(&g_bar_arrive, 1u) == NB - 1u) {
            g_bar_arrive = 0;
            __threadfence();
            g_bar_gen = gen + 1u;                // release
        } else {
            while (g_bar_gen == gen) { }         // co-resident: safe spin
        }
    }
    __syncthreads();
}

// ---------------- fused CSR build + fp16 conversion ----------------

__global__ void __launch_bounds__(TPB)
k_build(const int4*  __restrict__ src4,
        const int4*  __restrict__ dst4,
        const int*   __restrict__ src,
        const int*   __restrict__ dst,
        const float4* __restrict__ weight4,
        const float*  __restrict__ cj,
        int n_quads, int n_edges, int n_nodes)
{
    const int tid  = threadIdx.x;
    const int gtid = blockIdx.x * TPB + tid;
    const int nthr = NB * TPB;
    const int lane = tid & 31, wid = tid >> 5;

    // ---- phase 1a: histogram of dst, capturing per-edge ranks ----
    for (int q = gtid; q < n_quads; q += nthr) {
        int4 d = __ldg(dst4 + q);
        int4 r;
        r.x = atomicAdd(&g_counts[d.x], 1);
        r.y = atomicAdd(&g_counts[d.y], 1);
        r.z = atomicAdd(&g_counts[d.z], 1);
        r.w = atomicAdd(&g_counts[d.w], 1);
        ((int4*)g_rank)[q] = r;
    }
    {
        int rem = n_edges - n_quads * 4;
        if (gtid < rem) {
            int t = n_quads * 4 + gtid;
            g_rank[t] = atomicAdd(&g_counts[dst[t]], 1);
        }
    }

    // ---- phase 1b: W' = fp16(weight * cj), one uint4 per iteration ----
    {
        int total = n_nodes * (FEAT4 / 2);       // 16 uint4 per row
        for (int i = gtid; i < total; i += nthr) {
            int row = i >> 4;
            float s = __ldg(cj + row);
            float4 a = __ldg(weight4 + i * 2);
            float4 b = __ldg(weight4 + i * 2 + 1);
            __half2 h0 = __floats2half2_rn(a.x * s, a.y * s);
            __half2 h1 = __floats2half2_rn(a.z * s, a.w * s);
            __half2 h2 = __floats2half2_rn(b.x * s, b.y * s);
            __half2 h3 = __floats2half2_rn(b.z * s, b.w * s);
            uint4 p;
            p.x = *reinterpret_cast<unsigned int*>(&h0);
            p.y = *reinterpret_cast<unsigned int*>(&h1);
            p.z = *reinterpret_cast<unsigned int*>(&h2);
            p.w = *reinterpret_cast<unsigned int*>(&h3);
            reinterpret_cast<uint4*>(g_wh)[i] = p;
        }
    }

    grid_barrier();                              // counts final

    // ---- phase 2: block-local scan (one element per thread) ----
    __shared__ int warp_sums[32];
    __shared__ int s_prefix;
    int i = gtid;                                // NB*TPB = 151552 >= n_nodes
    int v = (i < n_nodes) ? g_counts[i] : 0;

    int x = v;                                   // inclusive warp scan
    #pragma unroll
    for (int o = 1; o < 32; o <<= 1) {
        int y = __shfl_up_sync(0xFFFFFFFFu, x, o);
        if (lane >= o) x += y;
    }
    if (lane == 31) warp_sums[wid] = x;
    __syncthreads();

    if (wid == 0) {
        int w = warp_sums[lane];
        #pragma unroll
        for (int o = 1; o < 32; o <<= 1) {
            int y = __shfl_up_sync(0xFFFFFFFFu, w, o);
            if (lane >= o) w += y;
        }
        warp_sums[lane] = w;                     // inclusive warp-total prefix
        if (lane == 31) g_blocksums[blockIdx.x] = w;   // block total
    }
    __syncthreads();

    grid_barrier();                              // all block totals visible

    // ---- phase 3: cross-block prefix, write offsets/cursor ----
    if (wid == 0) {
        int acc = 0;
        for (int b = lane; b < (int)blockIdx.x; b += 32)
            acc += g_blocksums[b];
        #pragma unroll
        for (int o = 16; o > 0; o >>= 1)
            acc += __shfl_down_sync(0xFFFFFFFFu, acc, o);
        if (lane == 0) s_prefix = acc;
    }
    __syncthreads();

    int warp_off = (wid > 0) ? warp_sums[wid - 1] : 0;
    if (i < n_nodes) {
        int excl = s_prefix + warp_off + x - v;
        g_offsets[i] = excl;                     // segment start
        g_cursor[i]  = excl + v;                 // segment end
    }

    grid_barrier();                              // offsets visible everywhere

    // ---- phase 4: scatter (atomic-free) ----
    for (int q = gtid; q < n_quads; q += nthr) {
        int4 s = __ldg(src4 + q);
        int4 d = __ldg(dst4 + q);
        int4 r = ((const int4*)g_rank)[q];
        g_edge_src[g_offsets[d.x] + r.x] = s.x;
        g_edge_src[g_offsets[d.y] + r.y] = s.y;
        g_edge_src[g_offsets[d.z] + r.z] = s.z;
        g_edge_src[g_offsets[d.w] + r.w] = s.w;
    }
    {
        int rem = n_edges - n_quads * 4;
        if (gtid < rem) {
            int t = n_quads * 4 + gtid;
            g_edge_src[g_offsets[dst[t]] + g_rank[t]] = src[t];
        }
    }
}

// ---------------- main gather-accumulate (unchanged, 44.7us measured) --------
// One warp per dst node; lane c owns halves [4c,4c+4) (one uint2 = 8B).
// 8 edges per main iteration; HADD2 pair pre-reduction; 32-bit indexing.

__device__ __forceinline__ void acc_pair(float4& acc, uint2 pa, uint2 pb) {
    __half2 lo = __hadd2(*reinterpret_cast<__half2*>(&pa.x),
                         *reinterpret_cast<__half2*>(&pb.x));
    __half2 hi = __hadd2(*reinterpret_cast<__half2*>(&pa.y),
                         *reinterpret_cast<__half2*>(&pb.y));
    float2 f0 = __half22float2(lo);
    float2 f1 = __half22float2(hi);
    acc.x += f0.x; acc.y += f0.y; acc.z += f1.x; acc.w += f1.y;
}

__device__ __forceinline__ void acc_single(float4& acc, uint2 p) {
    float2 f0 = __half22float2(*reinterpret_cast<__half2*>(&p.x));
    float2 f1 = __half22float2(*reinterpret_cast<__half2*>(&p.y));
    acc.x += f0.x; acc.y += f0.y; acc.z += f1.x; acc.w += f1.y;
}

__global__ void __launch_bounds__(256)
k_gather(const float* __restrict__ ci,
         float4*      __restrict__ out4,
         int n_nodes)
{
    int gid  = blockIdx.x * blockDim.x + threadIdx.x;
    int node = gid >> 5;
    int c    = gid & 31;
    if (node >= n_nodes) return;

    int base = g_offsets[node];
    int end  = g_cursor[node];

    float4 acc = make_float4(0.f, 0.f, 0.f, 0.f);

    int j = base;
    while (j < end && (j & 3)) {                 // align to int4 id loads
        uint2 p = __ldg(&g_wh[g_edge_src[j] * FEATH2 + c]);
        acc_single(acc, p);
        j++;
    }
    for (; j + 7 < end; j += 8) {                // 8 gathers in flight
        int4 sa = __ldg(reinterpret_cast<const int4*>(g_edge_src + j));
        int4 sb = __ldg(reinterpret_cast<const int4*>(g_edge_src + j + 4));
        uint2 p0 = __ldg(&g_wh[sa.x * FEATH2 + c]);
        uint2 p1 = __ldg(&g_wh[sa.y * FEATH2 + c]);
        uint2 p2 = __ldg(&g_wh[sa.z * FEATH2 + c]);
        uint2 p3 = __ldg(&g_wh[sa.w * FEATH2 + c]);
        uint2 p4 = __ldg(&g_wh[sb.x * FEATH2 + c]);
        uint2 p5 = __ldg(&g_wh[sb.y * FEATH2 + c]);
        uint2 p6 = __ldg(&g_wh[sb.z * FEATH2 + c]);
        uint2 p7 = __ldg(&g_wh[sb.w * FEATH2 + c]);
        acc_pair(acc, p0, p1);
        acc_pair(acc, p2, p3);
        acc_pair(acc, p4, p5);
        acc_pair(acc, p6, p7);
    }
    if (j + 3 < end) {
        int4 s4 = __ldg(reinterpret_cast<const int4*>(g_edge_src + j));
        uint2 p0 = __ldg(&g_wh[s4.x * FEATH2 + c]);
        uint2 p1 = __ldg(&g_wh[s4.y * FEATH2 + c]);
        uint2 p2 = __ldg(&g_wh[s4.z * FEATH2 + c]);
        uint2 p3 = __ldg(&g_wh[s4.w * FEATH2 + c]);
        acc_pair(acc, p0, p1);
        acc_pair(acc, p2, p3);
        j += 4;
    }
    for (; j < end; j++) {
        uint2 p = __ldg(&g_wh[g_edge_src[j] * FEATH2 + c]);
        acc_single(acc, p);
    }

    float m = __ldg(ci + node);
    acc.x *= m; acc.y *= m; acc.z *= m; acc.w *= m;
    out4[node * FEAT4 + c] = acc;

    // restore zero-counts invariant for the next graph replay
    if (c == 0) g_counts[node] = 0;
}

// ---------------- launch ----------------

extern "C" void kernel_launch(void* const* d_in, const int* in_sizes, int n_in,
                              void* d_out, int out_size)
{
    const float4* weight4 = (const float4*)d_in[0];
    const float*  cj      = (const float*)d_in[1];
    const float*  ci      = (const float*)d_in[2];
    const int*    src     = (const int*)d_in[3];
    const int*    dst     = (const int*)d_in[4];
    float4*       out4    = (float4*)d_out;

    int n_nodes = in_sizes[1];   // cj is [N,1]
    int n_edges = in_sizes[3];
    int n_quads = n_edges / 4;

    k_build<<<NB, TPB>>>((const int4*)src, (const int4*)dst, src, dst,
                         weight4, cj, n_quads, n_edges, n_nodes);

    int64_t total_threads = (int64_t)n_nodes * 32;
    int gather_blocks = (int)((total_threads + 255) / 256);
    k_gather<<<gather_blocks, 256>>>(ci, out4, n_nodes);
}